// round 6
// baseline (speedup 1.0000x reference)
#include <cuda_runtime.h>
#include <math.h>

#define PH 11
#define PW 11
#define SCALEF 0.0625f
#define FH 200
#define FW 200
#define NC 256
#define CH_STRIDE (FH * FW)   // 40000 elements
#define CPW 4
#define WARPS 8

// Block = one roi x 32 channels; warp = 4 channels.
// Rows are loaded COALESCED: lane j = feature column xbase+j (span of all 22
// x-samples fits in 32 columns: 10.5*bin_w <= 29.84, +1 hi corner -> idx<=31;
// and xbase+31 <= 193 < 200 so always in-bounds). One LDG.32 per channel-row,
// then per-sample x-interp value built with 2 dynamic-index shfl + FMA into a
// register row cache (rA/rB per channel). Monotone row reuse: off==cOff full
// reuse; off==cOff+FW shift B->A and load only rowB. Steady state = 2 FMA/ch.
__global__ __launch_bounds__(256) void roialign_maxpool_kernel(
    const float* __restrict__ feat,
    const float* __restrict__ rois,
    float* __restrict__ out)
{
    __shared__ int   s_off[2 * PH];
    __shared__ float s_ly[2 * PH];
    __shared__ float pooled[WARPS][CPW][PH][PW];

    const int k    = blockIdx.x;
    const int tid  = threadIdx.x;
    const int warp = tid >> 5;
    const int lane = tid & 31;
    const unsigned FULL = 0xffffffffu;

    const float x1 = __ldg(&rois[k * 5 + 1]) * SCALEF;
    const float y1 = __ldg(&rois[k * 5 + 2]) * SCALEF;
    const float x2 = __ldg(&rois[k * 5 + 3]) * SCALEF;
    const float y2 = __ldg(&rois[k * 5 + 4]) * SCALEF;
    const int   b  = (int)__ldg(&rois[k * 5 + 0]);

    const float bin_w = fmaxf(x2 - x1, 1.0f) * (1.0f / PW);
    const float bin_h = fmaxf(y2 - y1, 1.0f) * (1.0f / PH);

    // 22 y-sample rows once per block (input ranges guarantee no clamping)
    if (tid < 2 * PH) {
        float yc  = y1 + ((float)tid * 0.5f + 0.25f) * bin_h;
        int   ylo = (int)floorf(yc);
        s_off[tid] = ylo * FW;
        s_ly[tid]  = yc - (float)ylo;
    }

    // Per-lane sample geometry (lanes >=22 mirror sample 21; harmless)
    const int  l  = min(lane, 2 * PW - 1);
    const int  px = l >> 1;
    const int  sx = l & 1;
    const bool active = (lane < 2 * PW);

    float xc = x1 + ((float)px + 0.25f + 0.5f * (float)sx) * bin_w;
    const int   xlo = (int)floorf(xc);
    const float lx  = xc - (float)xlo;
    const float hx  = 1.0f - lx;

    const int xbase = __shfl_sync(FULL, xlo, 0);   // min over lanes (monotone)
    const int idx   = xlo - xbase;                 // gather index in [0,30]
    const int idx1  = idx + 1;                     // <= 31

    const int c0 = blockIdx.y * (WARPS * CPW) + warp * CPW;
    // column-lane load pointer: lane j reads column xbase+j of each row
    const float* __restrict__ fcol =
        feat + ((size_t)(b * NC + c0)) * CH_STRIDE + xbase + lane;

    __syncthreads();

    // X-interpolated row cache (rowA, rowB) per channel
    float rA0, rA1, rA2, rA3;
    float rB0, rB1, rB2, rB3;
    int   cOff = -0x40000000;
    float acc0 = 0.f, acc1 = 0.f, acc2 = 0.f, acc3 = 0.f;

#pragma unroll 2
    for (int t = 0; t < 2 * PH; ++t) {
        const int   off = s_off[t];
        const float ly  = s_ly[t];

        if (off != cOff) {                      // warp-uniform branch
            if (off == cOff + FW) {             // shift: rowB becomes rowA
                rA0 = rB0; rA1 = rB1; rA2 = rB2; rA3 = rB3;
            } else {                            // fresh rowA (coalesced)
                const float* __restrict__ p = fcol + off;
                float v0 = __ldg(p + 0 * CH_STRIDE);
                float v1 = __ldg(p + 1 * CH_STRIDE);
                float v2 = __ldg(p + 2 * CH_STRIDE);
                float v3 = __ldg(p + 3 * CH_STRIDE);
                rA0 = fmaf(lx, __shfl_sync(FULL, v0, idx1), hx * __shfl_sync(FULL, v0, idx));
                rA1 = fmaf(lx, __shfl_sync(FULL, v1, idx1), hx * __shfl_sync(FULL, v1, idx));
                rA2 = fmaf(lx, __shfl_sync(FULL, v2, idx1), hx * __shfl_sync(FULL, v2, idx));
                rA3 = fmaf(lx, __shfl_sync(FULL, v3, idx1), hx * __shfl_sync(FULL, v3, idx));
            }
            {                                   // rowB = next row (no clamp)
                const float* __restrict__ p = fcol + off + FW;
                float v0 = __ldg(p + 0 * CH_STRIDE);
                float v1 = __ldg(p + 1 * CH_STRIDE);
                float v2 = __ldg(p + 2 * CH_STRIDE);
                float v3 = __ldg(p + 3 * CH_STRIDE);
                rB0 = fmaf(lx, __shfl_sync(FULL, v0, idx1), hx * __shfl_sync(FULL, v0, idx));
                rB1 = fmaf(lx, __shfl_sync(FULL, v1, idx1), hx * __shfl_sync(FULL, v1, idx));
                rB2 = fmaf(lx, __shfl_sync(FULL, v2, idx1), hx * __shfl_sync(FULL, v2, idx));
                rB3 = fmaf(lx, __shfl_sync(FULL, v3, idx1), hx * __shfl_sync(FULL, v3, idx));
            }
            cOff = off;
        }

        // y-interp: 2 ops per channel
        float v0 = fmaf(ly, rB0 - rA0, rA0);
        float v1 = fmaf(ly, rB1 - rA1, rA1);
        float v2 = fmaf(ly, rB2 - rA2, rA2);
        float v3 = fmaf(ly, rB3 - rA3, rA3);

        if ((t & 1) == 0) {
            acc0 = v0; acc1 = v1; acc2 = v2; acc3 = v3;
        } else {
            acc0 += v0; acc1 += v1; acc2 += v2; acc3 += v3;
            acc0 += __shfl_xor_sync(FULL, acc0, 1);
            acc1 += __shfl_xor_sync(FULL, acc1, 1);
            acc2 += __shfl_xor_sync(FULL, acc2, 1);
            acc3 += __shfl_xor_sync(FULL, acc3, 1);
            const int py = t >> 1;
            if (active && (sx == 0)) {
                pooled[warp][0][py][px] = acc0 * 0.25f;
                pooled[warp][1][py][px] = acc1 * 0.25f;
                pooled[warp][2][py][px] = acc2 * 0.25f;
                pooled[warp][3][py][px] = acc3 * 0.25f;
            }
        }
    }
    __syncwarp();

    // 3x3 stride-2 maxpool over each 11x11 pooled tile -> 5x5
    if (lane < 25) {
        const int oy = lane / 5;
        const int ox = lane % 5;
#pragma unroll
        for (int j = 0; j < CPW; ++j) {
            float m = -INFINITY;
#pragma unroll
            for (int dy = 0; dy < 3; ++dy)
#pragma unroll
                for (int dx = 0; dx < 3; ++dx)
                    m = fmaxf(m, pooled[warp][j][2 * oy + dy][2 * ox + dx]);
            out[(((size_t)k * NC + (c0 + j)) * 5 + oy) * 5 + ox] = m;
        }
    }
}

extern "C" void kernel_launch(void* const* d_in, const int* in_sizes, int n_in,
                              void* d_out, int out_size)
{
    const float* feat = (const float*)d_in[0];
    const float* rois = (const float*)d_in[1];
    float* out = (float*)d_out;

    const int K = in_sizes[1] / 5;  // 512 rois

    dim3 grid(K, NC / (WARPS * CPW));   // (512, 8)
    dim3 block(256);
    roialign_maxpool_kernel<<<grid, block>>>(feat, rois, out);
}